// round 8
// baseline (speedup 1.0000x reference)
#include <cuda_runtime.h>
#include <cstdint>

// preds [B=8, N=16, C=4, H=128, W=256] f32, gt [8,4,128,256] f32, out scalar f32
#define CHW        131072
#define NCHW       (16 * CHW)
#define NPIX       1048576
#define GRID       148
#define NTHR       512                  // 16 warps, 2 pixels (float2) per thread
#define TILE_PX    1024
#define NTILES     1024                 // NPIX / TILE_PX
#define SLICE_B    4096                 // bytes per slice per stage (512 thr * 8B)
#define NSLICE     17                   // 16 preds + gt
#define STAGE_B    (NSLICE * SLICE_B)   // 69632
#define STAGES     3
#define SMEM_BYTES (STAGES * STAGE_B)   // 208896 <= 227KB

__device__ float        g_partials[GRID];
__device__ unsigned int g_done = 0;

__device__ __forceinline__ uint32_t smem_u32(const void* p) {
    uint32_t a;
    asm("{ .reg .u64 t; cvta.to.shared.u64 t, %1; cvt.u32.u64 %0, t; }" : "=r"(a) : "l"(p));
    return a;
}
__device__ __forceinline__ void cpa8(uint32_t dst, const float2* src) {
    asm volatile("cp.async.ca.shared.global [%0], [%1], 8;" :: "r"(dst), "l"(src) : "memory");
}
__device__ __forceinline__ void cpa_commit() {
    asm volatile("cp.async.commit_group;" ::: "memory");
}
template <int N>
__device__ __forceinline__ void cpa_wait() {
    asm volatile("cp.async.wait_group %0;" :: "n"(N) : "memory");
}

__device__ __forceinline__ void cas2(float2 &a, float2 &b) {
    float2 lo, hi;
    lo.x = fminf(a.x, b.x); hi.x = fmaxf(a.x, b.x);
    lo.y = fminf(a.y, b.y); hi.y = fmaxf(a.y, b.y);
    a = lo; b = hi;
}

// Issue this thread's 17 cp.async for tile tg into stage st (+ commit by caller)
__device__ __forceinline__ void issue_tile(const float* preds, const float* gt,
                                           int tg, int st, uint32_t sb, int tid) {
    const int b   = tg >> 7;                       // 128 tiles per batch image
    const int chw = (tg & 127) * TILE_PX;
    const uint32_t stage = sb + st * STAGE_B + tid * 8;
    const float2* ps = reinterpret_cast<const float2*>(preds) + ((b * NCHW + chw) >> 1) + tid;
    #pragma unroll
    for (int n = 0; n < 16; n++)
        cpa8(stage + n * SLICE_B, ps + ((n * CHW) >> 1));
    cpa8(stage + 16 * SLICE_B,
         reinterpret_cast<const float2*>(gt) + ((b * CHW + chw) >> 1) + tid);
}

__global__ __launch_bounds__(NTHR) void crps_cpa(const float* __restrict__ preds,
                                                 const float* __restrict__ gt,
                                                 float* __restrict__ out) {
    extern __shared__ char smem[];
    const uint32_t sb = smem_u32(smem);
    const int tid = threadIdx.x;
    const int bid = blockIdx.x;
    const int nt  = (NTILES - bid + GRID - 1) / GRID;   // 6 or 7 tiles

    // Prologue: 3 committed groups (tiles 0..2); no inter-warp sync anywhere
    #pragma unroll
    for (int j = 0; j < STAGES; j++) {
        if (j < nt) issue_tile(preds, gt, bid + j * GRID, j, sb, tid);
        cpa_commit();
    }

    float acc = 0.f;
    for (int i = 0; i < nt; i++) {
        const int st = i % STAGES;
        cpa_wait<2>();                 // groups up to tile i complete (per-warp)

        const char* stage = smem + st * STAGE_B;
        float2 v[16];
        #pragma unroll
        for (int n = 0; n < 16; n++)
            v[n] = *reinterpret_cast<const float2*>(stage + n * SLICE_B + tid * 8);
        const float2 g = *reinterpret_cast<const float2*>(stage + 16 * SLICE_B + tid * 8);

        // term1 consumes every value -> all LDS results register-resident after this
        float2 t1 = make_float2(0.f, 0.f);
        #pragma unroll
        for (int n = 0; n < 16; n++) {
            t1.x += fabsf(v[n].x - g.x);
            t1.y += fabsf(v[n].y - g.y);
        }

        // Refill this stage for tile i+3 immediately; overlaps the whole sort
        if (i + STAGES < nt) issue_tile(preds, gt, bid + (i + STAGES) * GRID, st, sb, tid);
        cpa_commit();

        // Green's 16-input 60-comparator sorting network (component-wise)
        cas2(v[0],v[1]);  cas2(v[2],v[3]);  cas2(v[4],v[5]);  cas2(v[6],v[7]);
        cas2(v[8],v[9]);  cas2(v[10],v[11]);cas2(v[12],v[13]);cas2(v[14],v[15]);
        cas2(v[0],v[2]);  cas2(v[4],v[6]);  cas2(v[8],v[10]); cas2(v[12],v[14]);
        cas2(v[1],v[3]);  cas2(v[5],v[7]);  cas2(v[9],v[11]); cas2(v[13],v[15]);
        cas2(v[0],v[4]);  cas2(v[8],v[12]); cas2(v[1],v[5]);  cas2(v[9],v[13]);
        cas2(v[2],v[6]);  cas2(v[10],v[14]);cas2(v[3],v[7]);  cas2(v[11],v[15]);
        cas2(v[0],v[8]);  cas2(v[1],v[9]);  cas2(v[2],v[10]); cas2(v[3],v[11]);
        cas2(v[4],v[12]); cas2(v[5],v[13]); cas2(v[6],v[14]); cas2(v[7],v[15]);
        cas2(v[5],v[10]); cas2(v[6],v[9]);  cas2(v[3],v[12]); cas2(v[13],v[14]);
        cas2(v[7],v[11]); cas2(v[1],v[2]);  cas2(v[4],v[8]);
        cas2(v[1],v[4]);  cas2(v[7],v[13]); cas2(v[2],v[8]);  cas2(v[11],v[14]);
        cas2(v[5],v[6]);  cas2(v[9],v[10]);
        cas2(v[2],v[4]);  cas2(v[11],v[13]);cas2(v[3],v[8]);  cas2(v[7],v[12]);
        cas2(v[6],v[8]);  cas2(v[10],v[12]);cas2(v[3],v[5]);  cas2(v[7],v[9]);
        cas2(v[3],v[4]);  cas2(v[5],v[6]);  cas2(v[7],v[8]);  cas2(v[9],v[10]);
        cas2(v[11],v[12]);
        cas2(v[6],v[7]);  cas2(v[8],v[9]);

        // term2: sum_{i<j}(x_j - x_i) = sum_k (2k-15) x_k
        float2 t2 = make_float2(0.f, 0.f);
        #pragma unroll
        for (int k = 0; k < 16; k++) {
            const float w = (float)(2 * k - 15);
            t2.x = fmaf(w, v[k].x, t2.x);
            t2.y = fmaf(w, v[k].y, t2.y);
        }

        const float c1 = 1.0f / (16.0f * (float)NPIX);
        const float c2 = 1.0f / (240.0f * (float)NPIX);
        acc += (t1.x + t1.y) * c1 - (t2.x + t2.y) * c2;
    }

    // Deterministic block reduction (16 warps)
    #pragma unroll
    for (int o = 16; o > 0; o >>= 1) acc += __shfl_down_sync(0xffffffffu, acc, o);
    __shared__ float s[NTHR / 32];
    if ((tid & 31) == 0) s[tid >> 5] = acc;
    __syncthreads();
    if (tid < 32) {
        float x = (tid < (NTHR / 32)) ? s[tid] : 0.f;
        #pragma unroll
        for (int o = 16; o > 0; o >>= 1) x += __shfl_down_sync(0xffffffffu, x, o);
        if (tid == 0) g_partials[bid] = x;
    }

    // Last-block final reduction (deterministic order; atomic only elects)
    __shared__ bool s_last;
    __threadfence();
    if (tid == 0) {
        unsigned int r = atomicAdd(&g_done, 1u);
        s_last = (r == (unsigned)(GRID - 1));
    }
    __syncthreads();
    if (s_last) {
        float a2 = (tid < GRID) ? __ldcg(&g_partials[tid]) : 0.f;
        #pragma unroll
        for (int o = 16; o > 0; o >>= 1) a2 += __shfl_down_sync(0xffffffffu, a2, o);
        __shared__ float s2[NTHR / 32];
        if ((tid & 31) == 0) s2[tid >> 5] = a2;
        __syncthreads();
        if (tid == 0) {
            float x = 0.f;
            #pragma unroll
            for (int w = 0; w < 5; w++) x += s2[w];   // 148 partial-threads span warps 0..4
            out[0] = x;
            g_done = 0;                               // reset for graph replay
        }
    }
}

extern "C" void kernel_launch(void* const* d_in, const int* in_sizes, int n_in,
                              void* d_out, int out_size) {
    const float* preds = (const float*)d_in[0];
    const float* gt    = (const float*)d_in[1];
    float* out = (float*)d_out;
    (void)in_sizes; (void)n_in; (void)out_size;
    cudaFuncSetAttribute(crps_cpa, cudaFuncAttributeMaxDynamicSharedMemorySize, SMEM_BYTES);
    crps_cpa<<<GRID, NTHR, SMEM_BYTES>>>(preds, gt, out);
}

// round 9
// speedup vs baseline: 1.1212x; 1.1212x over previous
#include <cuda_runtime.h>

// preds [B=8, N=16, C=4, H=128, W=256] f32, gt [8,4,128,256] f32, out scalar f32
#define CHW     131072              // C*H*W
#define NCHW    (16 * CHW)
#define NPIX    1048576             // B*C*H*W
#define NBLK    1024
#define NTHR    256                 // NBLK*NTHR*4 == NPIX (4 pixels/thread, float4)

__device__ float        g_partials[NBLK];
__device__ unsigned int g_done = 0;

__device__ __forceinline__ void cas4(float4 &a, float4 &b) {
    float4 lo, hi;
    lo.x = fminf(a.x, b.x); hi.x = fmaxf(a.x, b.x);
    lo.y = fminf(a.y, b.y); hi.y = fmaxf(a.y, b.y);
    lo.z = fminf(a.z, b.z); hi.z = fmaxf(a.z, b.z);
    lo.w = fminf(a.w, b.w); hi.w = fmaxf(a.w, b.w);
    a = lo; b = hi;
}

__global__ __launch_bounds__(NTHR) void crps_main(const float* __restrict__ preds,
                                                  const float* __restrict__ gt,
                                                  float* __restrict__ out) {
    const int t    = blockIdx.x * NTHR + threadIdx.x;   // 0 .. 262143
    const int b    = t >> 15;                           // t / (CHW/4)
    const int chw  = (t & 32767) << 2;                  // element offset within [C,H,W]

    const float4* pb = reinterpret_cast<const float4*>(preds + b * NCHW + chw);
    const float4  g  = *reinterpret_cast<const float4*>(gt + b * CHW + chw);

    // Front-batched ensemble loads: 16 independent LDG.128 (high MLP)
    float4 v[16];
    #pragma unroll
    for (int n = 0; n < 16; n++) v[n] = pb[n * (CHW / 4)];

    // term1: sum over ensemble of |p - g|
    float4 t1 = make_float4(0.f, 0.f, 0.f, 0.f);
    #pragma unroll
    for (int n = 0; n < 16; n++) {
        t1.x += fabsf(v[n].x - g.x);
        t1.y += fabsf(v[n].y - g.y);
        t1.z += fabsf(v[n].z - g.z);
        t1.w += fabsf(v[n].w - g.w);
    }

    // Green's 16-input 60-comparator sorting network, component-wise
    cas4(v[0],v[1]);  cas4(v[2],v[3]);  cas4(v[4],v[5]);  cas4(v[6],v[7]);
    cas4(v[8],v[9]);  cas4(v[10],v[11]);cas4(v[12],v[13]);cas4(v[14],v[15]);
    cas4(v[0],v[2]);  cas4(v[4],v[6]);  cas4(v[8],v[10]); cas4(v[12],v[14]);
    cas4(v[1],v[3]);  cas4(v[5],v[7]);  cas4(v[9],v[11]); cas4(v[13],v[15]);
    cas4(v[0],v[4]);  cas4(v[8],v[12]); cas4(v[1],v[5]);  cas4(v[9],v[13]);
    cas4(v[2],v[6]);  cas4(v[10],v[14]);cas4(v[3],v[7]);  cas4(v[11],v[15]);
    cas4(v[0],v[8]);  cas4(v[1],v[9]);  cas4(v[2],v[10]); cas4(v[3],v[11]);
    cas4(v[4],v[12]); cas4(v[5],v[13]); cas4(v[6],v[14]); cas4(v[7],v[15]);
    cas4(v[5],v[10]); cas4(v[6],v[9]);  cas4(v[3],v[12]); cas4(v[13],v[14]);
    cas4(v[7],v[11]); cas4(v[1],v[2]);  cas4(v[4],v[8]);
    cas4(v[1],v[4]);  cas4(v[7],v[13]); cas4(v[2],v[8]);  cas4(v[11],v[14]);
    cas4(v[5],v[6]);  cas4(v[9],v[10]);
    cas4(v[2],v[4]);  cas4(v[11],v[13]);cas4(v[3],v[8]);  cas4(v[7],v[12]);
    cas4(v[6],v[8]);  cas4(v[10],v[12]);cas4(v[3],v[5]);  cas4(v[7],v[9]);
    cas4(v[3],v[4]);  cas4(v[5],v[6]);  cas4(v[7],v[8]);  cas4(v[9],v[10]);
    cas4(v[11],v[12]);
    cas4(v[6],v[7]);  cas4(v[8],v[9]);

    // term2 via sorted values: sum_{i<j}(x_j - x_i) = sum_k (2k-15) x_k
    float4 t2 = make_float4(0.f, 0.f, 0.f, 0.f);
    #pragma unroll
    for (int k = 0; k < 16; k++) {
        const float w = (float)(2 * k - 15);
        t2.x = fmaf(w, v[k].x, t2.x);
        t2.y = fmaf(w, v[k].y, t2.y);
        t2.z = fmaf(w, v[k].z, t2.z);
        t2.w = fmaf(w, v[k].w, t2.w);
    }

    const float c1 = 1.0f / (16.0f * (float)NPIX);
    const float c2 = 1.0f / (240.0f * (float)NPIX);   // N*(N-1) = 240
    float val = (t1.x + t1.y + t1.z + t1.w) * c1
              - (t2.x + t2.y + t2.z + t2.w) * c2;

    // Deterministic block reduction (8 warps)
    #pragma unroll
    for (int o = 16; o > 0; o >>= 1) val += __shfl_down_sync(0xffffffffu, val, o);
    __shared__ float s[NTHR / 32];
    if ((threadIdx.x & 31) == 0) s[threadIdx.x >> 5] = val;
    __syncthreads();
    if (threadIdx.x < 32) {
        float x = (threadIdx.x < (NTHR / 32)) ? s[threadIdx.x] : 0.f;
        #pragma unroll
        for (int o = 4; o > 0; o >>= 1) x += __shfl_down_sync(0xffu, x, o);
        if (threadIdx.x == 0) g_partials[blockIdx.x] = x;
    }

    // Fused last-block final reduction (deterministic order; atomic only elects)
    __shared__ bool s_last;
    __threadfence();
    if (threadIdx.x == 0) {
        unsigned int r = atomicAdd(&g_done, 1u);
        s_last = (r == (unsigned)(NBLK - 1));
    }
    __syncthreads();
    if (s_last) {
        const int tid = threadIdx.x;
        float acc = 0.f;
        #pragma unroll
        for (int i = 0; i < NBLK / NTHR; i++)          // 4 reads, fixed order
            acc += __ldcg(&g_partials[tid + i * NTHR]);
        #pragma unroll
        for (int o = 16; o > 0; o >>= 1) acc += __shfl_down_sync(0xffffffffu, acc, o);
        __shared__ float s2[NTHR / 32];
        if ((tid & 31) == 0) s2[tid >> 5] = acc;
        __syncthreads();
        if (tid == 0) {
            out[0] = s2[0] + s2[1] + s2[2] + s2[3]
                   + s2[4] + s2[5] + s2[6] + s2[7];
            g_done = 0;                                // reset for next graph replay
        }
    }
}

extern "C" void kernel_launch(void* const* d_in, const int* in_sizes, int n_in,
                              void* d_out, int out_size) {
    const float* preds = (const float*)d_in[0];  // [8,16,4,128,256]
    const float* gt    = (const float*)d_in[1];  // [8,4,128,256]
    float* out = (float*)d_out;                  // scalar f32
    (void)in_sizes; (void)n_in; (void)out_size;
    crps_main<<<NBLK, NTHR>>>(preds, gt, out);
}

// round 10
// speedup vs baseline: 1.1255x; 1.0038x over previous
#include <cuda_runtime.h>

// preds [B=8, N=16, C=4, H=128, W=256] f32, gt [8,4,128,256] f32, out scalar f32
#define CHW      131072
#define NCHW     (16 * CHW)
#define NPIX     1048576
#define GRID     296                 // 2 CTAs/SM exactly: one persistent wave
#define NTHR     256
#define TILE_PX  512                 // 256 threads * 2 px (float2)
#define NTILES   2048                // NPIX / TILE_PX; 256 tiles per batch image

__device__ float        g_partials[GRID];
__device__ unsigned int g_done = 0;

__device__ __forceinline__ void cas2(float2 &a, float2 &b) {
    float2 lo, hi;
    lo.x = fminf(a.x, b.x); hi.x = fmaxf(a.x, b.x);
    lo.y = fminf(a.y, b.y); hi.y = fmaxf(a.y, b.y);
    a = lo; b = hi;
}

// Load one tile's 16 ensemble slices + gt into registers (17 independent LDG.64)
__device__ __forceinline__ void load_tile(const float* __restrict__ preds,
                                          const float* __restrict__ gt,
                                          int tg, int tid, float2* v, float2& g) {
    const int b    = tg >> 8;                         // 256 tiles per image
    const int off2 = ((tg & 255) << 8) + tid;         // float2 index within [C,H,W]
    const float2* ps = reinterpret_cast<const float2*>(preds) + ((b * NCHW) >> 1) + off2;
    #pragma unroll
    for (int n = 0; n < 16; n++) v[n] = ps[(n * CHW) >> 1];
    g = reinterpret_cast<const float2*>(gt)[((b * CHW) >> 1) + off2];
}

// term1 - term2 contribution for one tile held in registers
__device__ __forceinline__ float compute_tile(float2* v, const float2 g) {
    float2 t1 = make_float2(0.f, 0.f);
    #pragma unroll
    for (int n = 0; n < 16; n++) {
        t1.x += fabsf(v[n].x - g.x);
        t1.y += fabsf(v[n].y - g.y);
    }

    // Green's 16-input 60-comparator sorting network (component-wise)
    cas2(v[0],v[1]);  cas2(v[2],v[3]);  cas2(v[4],v[5]);  cas2(v[6],v[7]);
    cas2(v[8],v[9]);  cas2(v[10],v[11]);cas2(v[12],v[13]);cas2(v[14],v[15]);
    cas2(v[0],v[2]);  cas2(v[4],v[6]);  cas2(v[8],v[10]); cas2(v[12],v[14]);
    cas2(v[1],v[3]);  cas2(v[5],v[7]);  cas2(v[9],v[11]); cas2(v[13],v[15]);
    cas2(v[0],v[4]);  cas2(v[8],v[12]); cas2(v[1],v[5]);  cas2(v[9],v[13]);
    cas2(v[2],v[6]);  cas2(v[10],v[14]);cas2(v[3],v[7]);  cas2(v[11],v[15]);
    cas2(v[0],v[8]);  cas2(v[1],v[9]);  cas2(v[2],v[10]); cas2(v[3],v[11]);
    cas2(v[4],v[12]); cas2(v[5],v[13]); cas2(v[6],v[14]); cas2(v[7],v[15]);
    cas2(v[5],v[10]); cas2(v[6],v[9]);  cas2(v[3],v[12]); cas2(v[13],v[14]);
    cas2(v[7],v[11]); cas2(v[1],v[2]);  cas2(v[4],v[8]);
    cas2(v[1],v[4]);  cas2(v[7],v[13]); cas2(v[2],v[8]);  cas2(v[11],v[14]);
    cas2(v[5],v[6]);  cas2(v[9],v[10]);
    cas2(v[2],v[4]);  cas2(v[11],v[13]);cas2(v[3],v[8]);  cas2(v[7],v[12]);
    cas2(v[6],v[8]);  cas2(v[10],v[12]);cas2(v[3],v[5]);  cas2(v[7],v[9]);
    cas2(v[3],v[4]);  cas2(v[5],v[6]);  cas2(v[7],v[8]);  cas2(v[9],v[10]);
    cas2(v[11],v[12]);
    cas2(v[6],v[7]);  cas2(v[8],v[9]);

    float2 t2 = make_float2(0.f, 0.f);
    #pragma unroll
    for (int k = 0; k < 16; k++) {
        const float w = (float)(2 * k - 15);
        t2.x = fmaf(w, v[k].x, t2.x);
        t2.y = fmaf(w, v[k].y, t2.y);
    }

    const float c1 = 1.0f / (16.0f * (float)NPIX);
    const float c2 = 1.0f / (240.0f * (float)NPIX);   // N*(N-1) = 240
    return (t1.x + t1.y) * c1 - (t2.x + t2.y) * c2;
}

__global__ __launch_bounds__(NTHR) void crps_pers(const float* __restrict__ preds,
                                                  const float* __restrict__ gt,
                                                  float* __restrict__ out) {
    const int tid = threadIdx.x;
    const int bid = blockIdx.x;
    const int nt  = (NTILES - bid + GRID - 1) / GRID;   // 6 or 7 tiles, stride GRID

    float2 va[16], vb[16];
    float2 ga, gb;
    float  acc = 0.f;

    // Software pipeline: B-loads fly while A sorts (registers are the buffers)
    load_tile(preds, gt, bid, tid, va, ga);
    int i = 0;
    while (true) {
        if (i + 1 < nt) load_tile(preds, gt, bid + (i + 1) * GRID, tid, vb, gb);
        acc += compute_tile(va, ga);
        if (++i >= nt) break;
        if (i + 1 < nt) load_tile(preds, gt, bid + (i + 1) * GRID, tid, va, ga);
        acc += compute_tile(vb, gb);
        if (++i >= nt) break;
    }

    // Deterministic block reduction (8 warps)
    #pragma unroll
    for (int o = 16; o > 0; o >>= 1) acc += __shfl_down_sync(0xffffffffu, acc, o);
    __shared__ float s[NTHR / 32];
    if ((tid & 31) == 0) s[tid >> 5] = acc;
    __syncthreads();
    if (tid < 32) {
        float x = (tid < (NTHR / 32)) ? s[tid] : 0.f;
        #pragma unroll
        for (int o = 4; o > 0; o >>= 1) x += __shfl_down_sync(0xffu, x, o);
        if (tid == 0) g_partials[bid] = x;
    }

    // Fused last-block final reduction (deterministic order; atomic only elects)
    __shared__ bool s_last;
    __threadfence();
    if (tid == 0) {
        unsigned int r = atomicAdd(&g_done, 1u);
        s_last = (r == (unsigned)(GRID - 1));
    }
    __syncthreads();
    if (s_last) {
        float a2 = __ldcg(&g_partials[tid]);                       // 0..255
        if (tid < GRID - NTHR) a2 += __ldcg(&g_partials[tid + NTHR]); // 256..295
        #pragma unroll
        for (int o = 16; o > 0; o >>= 1) a2 += __shfl_down_sync(0xffffffffu, a2, o);
        __shared__ float s2[NTHR / 32];
        if ((tid & 31) == 0) s2[tid >> 5] = a2;
        __syncthreads();
        if (tid == 0) {
            out[0] = s2[0] + s2[1] + s2[2] + s2[3]
                   + s2[4] + s2[5] + s2[6] + s2[7];
            g_done = 0;                                // reset for next graph replay
        }
    }
}

extern "C" void kernel_launch(void* const* d_in, const int* in_sizes, int n_in,
                              void* d_out, int out_size) {
    const float* preds = (const float*)d_in[0];  // [8,16,4,128,256]
    const float* gt    = (const float*)d_in[1];  // [8,4,128,256]
    float* out = (float*)d_out;                  // scalar f32
    (void)in_sizes; (void)n_in; (void)out_size;
    crps_pers<<<GRID, NTHR>>>(preds, gt, out);
}

// round 12
// speedup vs baseline: 1.2786x; 1.1361x over previous
#include <cuda_runtime.h>
#include <cuda_fp16.h>

// preds [B=8, N=16, C=4, H=128, W=256] f32, gt [8,4,128,256] f32, out scalar f32
#define CHW     131072
#define NCHW    (16 * CHW)
#define NPIX    1048576
#define NBLK    1024
#define NTHR    256                 // NBLK*NTHR*4 == NPIX (4 px/thread, float4)

__device__ float        g_partials[NBLK];
__device__ unsigned int g_done = 0;

// Exact packed compare-and-swap on 2 fp16 values (HMNMX2, alu pipe, rt=2)
__device__ __forceinline__ void cash(__half2 &a, __half2 &b) {
    const __half2 lo = __hmin2(a, b);
    const __half2 hi = __hmax2(a, b);
    a = lo; b = hi;
}

// Green's 16-input 60-comparator sorting network on half2 (2 pixels at once)
__device__ __forceinline__ void sort16h(__half2 v[16]) {
    cash(v[0],v[1]);  cash(v[2],v[3]);  cash(v[4],v[5]);  cash(v[6],v[7]);
    cash(v[8],v[9]);  cash(v[10],v[11]);cash(v[12],v[13]);cash(v[14],v[15]);
    cash(v[0],v[2]);  cash(v[4],v[6]);  cash(v[8],v[10]); cash(v[12],v[14]);
    cash(v[1],v[3]);  cash(v[5],v[7]);  cash(v[9],v[11]); cash(v[13],v[15]);
    cash(v[0],v[4]);  cash(v[8],v[12]); cash(v[1],v[5]);  cash(v[9],v[13]);
    cash(v[2],v[6]);  cash(v[10],v[14]);cash(v[3],v[7]);  cash(v[11],v[15]);
    cash(v[0],v[8]);  cash(v[1],v[9]);  cash(v[2],v[10]); cash(v[3],v[11]);
    cash(v[4],v[12]); cash(v[5],v[13]); cash(v[6],v[14]); cash(v[7],v[15]);
    cash(v[5],v[10]); cash(v[6],v[9]);  cash(v[3],v[12]); cash(v[13],v[14]);
    cash(v[7],v[11]); cash(v[1],v[2]);  cash(v[4],v[8]);
    cash(v[1],v[4]);  cash(v[7],v[13]); cash(v[2],v[8]);  cash(v[11],v[14]);
    cash(v[5],v[6]);  cash(v[9],v[10]);
    cash(v[2],v[4]);  cash(v[11],v[13]);cash(v[3],v[8]);  cash(v[7],v[12]);
    cash(v[6],v[8]);  cash(v[10],v[12]);cash(v[3],v[5]);  cash(v[7],v[9]);
    cash(v[3],v[4]);  cash(v[5],v[6]);  cash(v[7],v[8]);  cash(v[9],v[10]);
    cash(v[11],v[12]);
    cash(v[6],v[7]);  cash(v[8],v[9]);
}

__global__ __launch_bounds__(NTHR) void crps_main(const float* __restrict__ preds,
                                                  const float* __restrict__ gt,
                                                  float* __restrict__ out) {
    const int t   = blockIdx.x * NTHR + threadIdx.x;    // 0 .. 262143
    const int b   = t >> 15;
    const int chw = (t & 32767) << 2;

    const float4* pb = reinterpret_cast<const float4*>(preds + b * NCHW + chw);
    const float4  g  = *reinterpret_cast<const float4*>(gt + b * CHW + chw);

    // Front-batched ensemble loads: 16 independent LDG.128
    float4 v[16];
    #pragma unroll
    for (int n = 0; n < 16; n++) v[n] = pb[n * (CHW / 4)];

    // term1 in full f32 on the fma pipe; pack to half2 lanes as we go
    float4 t1 = make_float4(0.f, 0.f, 0.f, 0.f);
    __half2 ha[16], hb[16];                     // lane a = (x,y), lane b = (z,w)
    #pragma unroll
    for (int n = 0; n < 16; n++) {
        t1.x += fabsf(v[n].x - g.x);
        t1.y += fabsf(v[n].y - g.y);
        t1.z += fabsf(v[n].z - g.z);
        t1.w += fabsf(v[n].w - g.w);
        ha[n] = __floats2half2_rn(v[n].x, v[n].y);
        hb[n] = __floats2half2_rn(v[n].z, v[n].w);
    }

    // Exact sort of f16-rounded values (HMNMX2: selection, no rounding)
    sort16h(ha);
    sort16h(hb);

    // term2 = sum_k (2k-15) x_k  =  sum_{k<8} (2k-15)(x_k - x_{15-k})
    float4 t2 = make_float4(0.f, 0.f, 0.f, 0.f);
    #pragma unroll
    for (int k = 0; k < 8; k++) {
        const float w = (float)(2 * k - 15);
        const float2 da = __half22float2(__hsub2(ha[k], ha[15 - k]));
        const float2 db = __half22float2(__hsub2(hb[k], hb[15 - k]));
        t2.x = fmaf(w, da.x, t2.x);
        t2.y = fmaf(w, da.y, t2.y);
        t2.z = fmaf(w, db.x, t2.z);
        t2.w = fmaf(w, db.y, t2.w);
    }

    const float c1 = 1.0f / (16.0f * (float)NPIX);
    const float c2 = 1.0f / (240.0f * (float)NPIX);     // N*(N-1) = 240
    float val = (t1.x + t1.y + t1.z + t1.w) * c1
              - (t2.x + t2.y + t2.z + t2.w) * c2;

    // Deterministic block reduction (8 warps)
    #pragma unroll
    for (int o = 16; o > 0; o >>= 1) val += __shfl_down_sync(0xffffffffu, val, o);
    __shared__ float s[NTHR / 32];
    if ((threadIdx.x & 31) == 0) s[threadIdx.x >> 5] = val;
    __syncthreads();
    if (threadIdx.x < 32) {
        float x = (threadIdx.x < (NTHR / 32)) ? s[threadIdx.x] : 0.f;
        #pragma unroll
        for (int o = 4; o > 0; o >>= 1) x += __shfl_down_sync(0xffu, x, o);
        if (threadIdx.x == 0) g_partials[blockIdx.x] = x;
    }

    // Fused last-block final reduction (deterministic order; atomic only elects)
    __shared__ bool s_last;
    __threadfence();
    if (threadIdx.x == 0) {
        unsigned int r = atomicAdd(&g_done, 1u);
        s_last = (r == (unsigned)(NBLK - 1));
    }
    __syncthreads();
    if (s_last) {
        const int tid = threadIdx.x;
        float acc = 0.f;
        #pragma unroll
        for (int i = 0; i < NBLK / NTHR; i++)          // 4 reads, fixed order
            acc += __ldcg(&g_partials[tid + i * NTHR]);
        #pragma unroll
        for (int o = 16; o > 0; o >>= 1) acc += __shfl_down_sync(0xffffffffu, acc, o);
        __shared__ float s2[NTHR / 32];
        if ((tid & 31) == 0) s2[tid >> 5] = acc;
        __syncthreads();
        if (tid == 0) {
            out[0] = s2[0] + s2[1] + s2[2] + s2[3]
                   + s2[4] + s2[5] + s2[6] + s2[7];
            g_done = 0;                                // reset for next graph replay
        }
    }
}

extern "C" void kernel_launch(void* const* d_in, const int* in_sizes, int n_in,
                              void* d_out, int out_size) {
    const float* preds = (const float*)d_in[0];  // [8,16,4,128,256]
    const float* gt    = (const float*)d_in[1];  // [8,4,128,256]
    float* out = (float*)d_out;                  // scalar f32
    (void)in_sizes; (void)n_in; (void)out_size;
    crps_main<<<NBLK, NTHR>>>(preds, gt, out);
}